// round 2
// baseline (speedup 1.0000x reference)
#include <cuda_runtime.h>
#include <math.h>

// Problem constants (fixed-shape problem)
#define NROWS 8192
#define DIM   512
#define NCLS  64
#define NB    64          // 8192 / 128 block-columns
#define NTRI  2080        // 64*65/2 upper-triangular blocks
#define INV_T 14.285714285714286f  // 1/0.07

// ---------------- scratch (__device__ globals; no allocation) ----------------
__device__ float g_fnorm[NROWS * DIM];     // 16 MB normalized features
__device__ float g_Epart[NB][NROWS];       // 2 MB  per-(colblock,row) exp partial sums
__device__ float g_S[NCLS * DIM];          // class sums of normalized rows
__device__ int   g_cnt[NCLS];              // rows per class
__device__ int   g_glab[NROWS];            // group label per row
__device__ float g_psamp[NROWS];
__device__ int   g_validv[NROWS];

// ---------------- 1. normalize rows + group labels ----------------
__global__ void norm_kernel(const float* __restrict__ feat,
                            const int* __restrict__ labels,
                            const int* __restrict__ kptr) {
    int row = blockIdx.x;
    const float* fr = feat + (size_t)row * DIM;
    float s = 0.f;
    for (int d = threadIdx.x; d < DIM; d += blockDim.x) {
        float v = fr[d];
        s += v * v;
    }
    __shared__ float sh[4];
    #pragma unroll
    for (int o = 16; o; o >>= 1) s += __shfl_xor_sync(0xffffffffu, s, o);
    if ((threadIdx.x & 31) == 0) sh[threadIdx.x >> 5] = s;
    __syncthreads();
    float tot = sh[0] + sh[1] + sh[2] + sh[3];
    float inv = 1.0f / fmaxf(sqrtf(tot), 1e-12f);
    for (int d = threadIdx.x; d < DIM; d += blockDim.x)
        g_fnorm[(size_t)row * DIM + d] = fr[d] * inv;
    if (threadIdx.x == 0) {
        int k = kptr[0];
        g_glab[row] = labels[(row / k) * k];
    }
}

// ---------------- 2. per-class sums of normalized rows ----------------
__global__ void classsum_kernel() {
    int c = blockIdx.x;              // 64 blocks
    __shared__ int lab_sh[NROWS];    // 32 KB
    for (int i = threadIdx.x; i < NROWS; i += blockDim.x) lab_sh[i] = g_glab[i];
    __syncthreads();
    int d = threadIdx.x;             // blockDim = 512
    float acc = 0.f;
    int count = 0;
    for (int i = 0; i < NROWS; i++) {
        if (lab_sh[i] == c) {
            acc += g_fnorm[(size_t)i * DIM + d];
            count++;
        }
    }
    g_S[c * DIM + d] = acc;
    if (d == 0) g_cnt[c] = count;
}

// ---------------- 3. triangular fused GEMM + exp row/col sums ----------------
// C = fnorm * fnorm^T (128x128 tiles), epilogue e = exp((c-1)/T), diag excluded.
// Off-diagonal tiles also accumulate column sums (symmetric contribution).
__global__ __launch_bounds__(256, 2) void simexp_kernel() {
    // map linear block index -> upper-triangular (by, bx), bx >= by
    int t = blockIdx.x;
    int by = 0;
    while (t >= NB - by) { t -= NB - by; by++; }
    int bx = by + t;
    bool diag = (bx == by);

    __shared__ float As[16][128];
    __shared__ float Bs[16][128];
    __shared__ float cbuf[128][17];   // col-sum reduction buffer (padded)

    int tid = threadIdx.x;
    int tm = tid >> 4;        // 0..15 : row group
    int tn = tid & 15;        // 0..15 : col group

    float acc[8][8];
    #pragma unroll
    for (int i = 0; i < 8; i++)
        #pragma unroll
        for (int j = 0; j < 8; j++) acc[i][j] = 0.f;

    int lr = tid >> 2;            // 0..63 : load row
    int lc = (tid & 3) * 4;       // 0,4,8,12 : k offset
    const float* Abase = g_fnorm + (size_t)(by * 128) * DIM;
    const float* Bbase = g_fnorm + (size_t)(bx * 128) * DIM;

    for (int kb = 0; kb < DIM; kb += 16) {
        float4 a0 = *(const float4*)(Abase + (size_t)lr * DIM + kb + lc);
        float4 a1 = *(const float4*)(Abase + (size_t)(lr + 64) * DIM + kb + lc);
        float4 b0 = *(const float4*)(Bbase + (size_t)lr * DIM + kb + lc);
        float4 b1 = *(const float4*)(Bbase + (size_t)(lr + 64) * DIM + kb + lc);
        __syncthreads();  // all reads of previous tile complete
        As[lc + 0][lr] = a0.x; As[lc + 1][lr] = a0.y; As[lc + 2][lr] = a0.z; As[lc + 3][lr] = a0.w;
        As[lc + 0][lr + 64] = a1.x; As[lc + 1][lr + 64] = a1.y; As[lc + 2][lr + 64] = a1.z; As[lc + 3][lr + 64] = a1.w;
        Bs[lc + 0][lr] = b0.x; Bs[lc + 1][lr] = b0.y; Bs[lc + 2][lr] = b0.z; Bs[lc + 3][lr] = b0.w;
        Bs[lc + 0][lr + 64] = b1.x; Bs[lc + 1][lr + 64] = b1.y; Bs[lc + 2][lr + 64] = b1.z; Bs[lc + 3][lr + 64] = b1.w;
        __syncthreads();
        #pragma unroll
        for (int kk = 0; kk < 16; kk++) {
            float a[8], b[8];
            *(float4*)&a[0] = *(const float4*)&As[kk][tm * 8];
            *(float4*)&a[4] = *(const float4*)&As[kk][tm * 8 + 4];
            *(float4*)&b[0] = *(const float4*)&Bs[kk][tn * 8];
            *(float4*)&b[4] = *(const float4*)&Bs[kk][tn * 8 + 4];
            #pragma unroll
            for (int i = 0; i < 8; i++)
                #pragma unroll
                for (int j = 0; j < 8; j++)
                    acc[i][j] = fmaf(a[i], b[j], acc[i][j]);
        }
    }

    // ---- epilogue: e = exp((c-1)/T); row sums (this block's rows),
    //                 col sums (transpose contribution) ----
    float rowp[8], colp[8];
    #pragma unroll
    for (int i = 0; i < 8; i++) { rowp[i] = 0.f; colp[i] = 0.f; }
    #pragma unroll
    for (int i = 0; i < 8; i++) {
        #pragma unroll
        for (int j = 0; j < 8; j++) {
            float e = __expf((acc[i][j] - 1.0f) * INV_T);
            if (diag && (tm * 8 + i) == (tn * 8 + j)) e = 0.f;  // exclude self
            rowp[i] += e;
            colp[j] += e;
        }
    }

    // row sums: reduce across tn (lane bits 0..3)
    #pragma unroll
    for (int o = 8; o; o >>= 1)
        #pragma unroll
        for (int i = 0; i < 8; i++)
            rowp[i] += __shfl_xor_sync(0xffffffffu, rowp[i], o);
    if (tn == 0) {
        #pragma unroll
        for (int i = 0; i < 8; i++)
            g_Epart[bx][by * 128 + tm * 8 + i] = rowp[i];
    }

    // col sums: only for strictly-off-diagonal tiles (rows of bx-block, colblock by)
    if (!diag) {
        #pragma unroll
        for (int j = 0; j < 8; j++) cbuf[tn * 8 + j][tm] = colp[j];
        __syncthreads();
        if (tid < 128) {
            float s = 0.f;
            #pragma unroll
            for (int m = 0; m < 16; m++) s += cbuf[tid][m];
            g_Epart[by][bx * 128 + tid] = s;
        }
    }
}

// ---------------- 4. per-row finalize ----------------
__global__ void finalize_kernel() {
    int warp = threadIdx.x >> 5, lane = threadIdx.x & 31;
    int row = blockIdx.x * 8 + warp;

    float E = g_Epart[lane][row] + g_Epart[lane + 32][row];

    int gl = g_glab[row];
    const float* f = g_fnorm + (size_t)row * DIM;
    const float* s = g_S + gl * DIM;
    float dss = 0.f, dii = 0.f;
    for (int d = lane; d < DIM; d += 32) {
        float fv = f[d];
        dss += fv * s[d];
        dii += fv * fv;
    }
    #pragma unroll
    for (int o = 16; o; o >>= 1) {
        E   += __shfl_xor_sync(0xffffffffu, E, o);
        dss += __shfl_xor_sync(0xffffffffu, dss, o);
        dii += __shfl_xor_sync(0xffffffffu, dii, o);
    }
    if (lane == 0) {
        int c = g_cnt[gl] - 1;                 // positives (same group-label, != self)
        float P = (dss - dii) * INV_T;         // sum of sim over positives
        float denom = E + 1e-8f;               // diag already excluded
        float cf = (float)c;
        float cm = fmaxf(cf, 1.0f);
        // mean log prob over positives with m = 1/T:
        float mean = (P - cf * INV_T - cf * logf(denom)) / cm;
        g_psamp[row] = (c > 0) ? -mean : 0.0f;
        g_validv[row] = (c > 0) ? 1 : 0;
    }
}

// ---------------- 5. final scalar reduce ----------------
__global__ void reduce_kernel(float* __restrict__ out) {
    __shared__ float shs[32];
    __shared__ int   shv[32];
    float s = 0.f;
    int v = 0;
    for (int i = threadIdx.x; i < NROWS; i += blockDim.x) {
        s += g_psamp[i];
        v += g_validv[i];
    }
    #pragma unroll
    for (int o = 16; o; o >>= 1) {
        s += __shfl_xor_sync(0xffffffffu, s, o);
        v += __shfl_xor_sync(0xffffffffu, v, o);
    }
    int wid = threadIdx.x >> 5, lane = threadIdx.x & 31;
    if (lane == 0) { shs[wid] = s; shv[wid] = v; }
    __syncthreads();
    if (threadIdx.x == 0) {
        float ts = 0.f; int tv = 0;
        int nw = blockDim.x >> 5;
        for (int w = 0; w < nw; w++) { ts += shs[w]; tv += shv[w]; }
        out[0] = ts / fmaxf((float)tv, 1.0f);
    }
}

// ---------------- launch ----------------
extern "C" void kernel_launch(void* const* d_in, const int* in_sizes, int n_in,
                              void* d_out, int out_size) {
    const float* feat   = (const float*)d_in[0];
    const int*   labels = (const int*)d_in[1];
    const int*   kptr   = (const int*)d_in[2];
    float* out = (float*)d_out;

    norm_kernel<<<NROWS, 128>>>(feat, labels, kptr);
    classsum_kernel<<<NCLS, 512>>>();
    simexp_kernel<<<NTRI, 256>>>();
    finalize_kernel<<<NROWS / 8, 256>>>();
    reduce_kernel<<<1, 1024>>>(out);
}

// round 4
// speedup vs baseline: 5.3834x; 5.3834x over previous
#include <cuda_runtime.h>
#include <cuda_bf16.h>
#include <cstdint>
#include <math.h>

// Problem constants
#define NROWS 8192
#define DIM   512
#define NCLS  64
#define NB    64          // 8192/128 block-cols
#define NTRI  2080        // 64*65/2 triangular tiles
#define NSLICE 64
#define INV_T 14.285714285714286f

// ---------------- scratch ----------------
__device__ float g_fnorm[NROWS * DIM];                       // 16 MB fp32 normalized
__device__ alignas(128) __nv_bfloat16 g_fbf16[NROWS * DIM];  // 8 MB bf16 normalized
__device__ float g_Epart[NB][NROWS];                         // 2 MB exp partial sums
__device__ float g_Spart[NSLICE][NCLS * DIM];                // 8 MB class partials
__device__ float g_S[NCLS * DIM];
__device__ int   g_cnt[NCLS];
__device__ int   g_glab[NROWS];
__device__ float g_psamp[NROWS];
__device__ int   g_validv[NROWS];

// ---------------- helpers ----------------
__device__ __forceinline__ uint32_t smem_u32(const void* p) {
    uint32_t a;
    asm("{ .reg .u64 t; cvta.to.shared.u64 t, %1; cvt.u32.u64 %0, t; }" : "=r"(a) : "l"(p));
    return a;
}
__device__ __forceinline__ void cp16(uint32_t dst, const void* src) {
    asm volatile("cp.async.cg.shared.global [%0], [%1], 16;" :: "r"(dst), "l"(src) : "memory");
}
#define CP_COMMIT() asm volatile("cp.async.commit_group;" ::: "memory")
#define CP_WAIT(n)  asm volatile("cp.async.wait_group %0;" :: "n"(n) : "memory")

__device__ __forceinline__ void ldsm_x4(uint32_t& r0, uint32_t& r1, uint32_t& r2, uint32_t& r3,
                                        uint32_t addr) {
    asm volatile("ldmatrix.sync.aligned.m8n8.x4.shared.b16 {%0,%1,%2,%3}, [%4];"
                 : "=r"(r0), "=r"(r1), "=r"(r2), "=r"(r3) : "r"(addr));
}
__device__ __forceinline__ void ldsm_x2(uint32_t& r0, uint32_t& r1, uint32_t addr) {
    asm volatile("ldmatrix.sync.aligned.m8n8.x2.shared.b16 {%0,%1}, [%2];"
                 : "=r"(r0), "=r"(r1) : "r"(addr));
}
__device__ __forceinline__ void mma16816(float* c, const uint32_t* a, const uint32_t* b) {
    asm volatile("mma.sync.aligned.m16n8k16.row.col.f32.bf16.bf16.f32 "
                 "{%0,%1,%2,%3}, {%4,%5,%6,%7}, {%8,%9}, {%0,%1,%2,%3};"
                 : "+f"(c[0]), "+f"(c[1]), "+f"(c[2]), "+f"(c[3])
                 : "r"(a[0]), "r"(a[1]), "r"(a[2]), "r"(a[3]), "r"(b[0]), "r"(b[1]));
}

// ---------------- 1. normalize + bf16 + group labels ----------------
__global__ void norm_kernel(const float* __restrict__ feat,
                            const int* __restrict__ labels,
                            const int* __restrict__ kptr) {
    int row = blockIdx.x;
    const float* fr = feat + (size_t)row * DIM;
    float s = 0.f;
    for (int d = threadIdx.x; d < DIM; d += blockDim.x) {
        float v = fr[d];
        s += v * v;
    }
    __shared__ float sh[4];
    #pragma unroll
    for (int o = 16; o; o >>= 1) s += __shfl_xor_sync(0xffffffffu, s, o);
    if ((threadIdx.x & 31) == 0) sh[threadIdx.x >> 5] = s;
    __syncthreads();
    float tot = sh[0] + sh[1] + sh[2] + sh[3];
    float inv = 1.0f / fmaxf(sqrtf(tot), 1e-12f);
    for (int d = threadIdx.x; d < DIM; d += blockDim.x) {
        float v = fr[d] * inv;
        g_fnorm[(size_t)row * DIM + d] = v;
        g_fbf16[(size_t)row * DIM + d] = __float2bfloat16_rn(v);
    }
    if (threadIdx.x == 0) {
        int k = kptr[0];
        g_glab[row] = labels[(row / k) * k];
    }
}

// ---------------- 2a. class partial sums over row slices ----------------
__global__ void classpart_kernel() {
    extern __shared__ float accsh[];       // [NCLS * DIM] = 128 KB
    int slice = blockIdx.x, tid = threadIdx.x;
    for (int i = tid; i < NCLS * DIM; i += blockDim.x) accsh[i] = 0.f;
    __syncthreads();
    for (int r = 0; r < NROWS / NSLICE; r++) {
        int row = slice * (NROWS / NSLICE) + r;
        int lab = g_glab[row];
        accsh[lab * DIM + tid] += g_fnorm[(size_t)row * DIM + tid];
    }
    __syncthreads();
    for (int i = tid; i < NCLS * DIM; i += blockDim.x) g_Spart[slice][i] = accsh[i];
}

// ---------------- 2b. reduce partials + counts ----------------
__global__ void classred_kernel() {
    int c = blockIdx.x, d = threadIdx.x;   // 64 blocks x 512
    float s = 0.f;
    for (int sl = 0; sl < NSLICE; sl++) s += g_Spart[sl][c * DIM + d];
    g_S[c * DIM + d] = s;
}
__global__ void count_kernel() {
    __shared__ int cnt[NCLS];
    if (threadIdx.x < NCLS) cnt[threadIdx.x] = 0;
    __syncthreads();
    for (int i = threadIdx.x; i < NROWS; i += blockDim.x)
        atomicAdd(&cnt[g_glab[i]], 1);
    __syncthreads();
    if (threadIdx.x < NCLS) g_cnt[threadIdx.x] = cnt[threadIdx.x];
}

// ---------------- 3. HMMA triangular GEMM + exp row/col sums ----------------
// 128x128 tile per CTA, 8 warps in 2x4 grid, each warp 64x32 via m16n8k16.
// BK=32 (64B/row chunk), double-buffered cp.async. Rows padded to 80B.
#define ROWPADB 80
#define STAGEB  (128 * ROWPADB)

__global__ __launch_bounds__(256, 2) void simexp_mma() {
    __shared__ alignas(128) __nv_bfloat16 As[2][128][ROWPADB / 2];
    __shared__ alignas(128) __nv_bfloat16 Bs[2][128][ROWPADB / 2];
    __shared__ float rbuf[128][4];
    __shared__ float cbuf[128][2];

    int t = blockIdx.x, by = 0;
    while (t >= NB - by) { t -= NB - by; by++; }
    int bx = by + t;
    bool diag = (bx == by);

    int tid = threadIdx.x, lane = tid & 31, wid = tid >> 5;
    int wm = wid >> 2, wn = wid & 3;            // 2x4 warp grid

    uint32_t sA = smem_u32(As), sB = smem_u32(Bs);

    // loader mapping: 4 threads per row (16B chunks), rows lr and lr+64
    int lr  = tid >> 2;
    int lco = (tid & 3) * 16;
    const char* Ag = (const char*)(g_fbf16 + (size_t)(by * 128) * DIM);
    const char* Bg = (const char*)(g_fbf16 + (size_t)(bx * 128) * DIM);

    #define LOADC(st, k) do {                                                         \
        int kbyte = (k) * 64;                                                         \
        _Pragma("unroll")                                                             \
        for (int h = 0; h < 2; h++) {                                                 \
            int r = lr + 64 * h;                                                      \
            cp16(sA + (st) * STAGEB + r * ROWPADB + lco, Ag + (size_t)r * 1024 + kbyte + lco); \
            cp16(sB + (st) * STAGEB + r * ROWPADB + lco, Bg + (size_t)r * 1024 + kbyte + lco); \
        }                                                                             \
        CP_COMMIT();                                                                  \
    } while (0)

    float acc[4][4][4];
    #pragma unroll
    for (int i = 0; i < 4; i++)
        #pragma unroll
        for (int j = 0; j < 4; j++)
            #pragma unroll
            for (int v = 0; v < 4; v++) acc[i][j][v] = 0.f;

    LOADC(0, 0);
    LOADC(1, 1);

    for (int k = 0; k < 16; k++) {
        if (k < 15) CP_WAIT(1); else CP_WAIT(0);
        __syncthreads();
        int st = k & 1;
        uint32_t aBase = sA + st * STAGEB;
        uint32_t bBase = sB + st * STAGEB;
        #pragma unroll
        for (int ks = 0; ks < 2; ks++) {
            uint32_t a[4][4], b[4][2];
            #pragma unroll
            for (int mt = 0; mt < 4; mt++) {
                uint32_t addr = aBase + (uint32_t)(wm * 64 + mt * 16 + (lane & 15)) * ROWPADB
                              + ks * 32 + ((lane >> 4) & 1) * 16;
                ldsm_x4(a[mt][0], a[mt][1], a[mt][2], a[mt][3], addr);
            }
            #pragma unroll
            for (int nt = 0; nt < 4; nt++) {
                uint32_t addr = bBase + (uint32_t)(wn * 32 + nt * 8 + (lane & 7)) * ROWPADB
                              + ks * 32 + ((lane >> 3) & 1) * 16;
                ldsm_x2(b[nt][0], b[nt][1], addr);
            }
            #pragma unroll
            for (int mt = 0; mt < 4; mt++)
                #pragma unroll
                for (int nt = 0; nt < 4; nt++)
                    mma16816(acc[mt][nt], a[mt], b[nt]);
        }
        __syncthreads();
        if (k + 2 < 16) LOADC(st, k + 2);
    }

    // ---- epilogue: e = exp((c-1)/T), row + col partial sums ----
    float rs[4][2], cs[4][2];
    #pragma unroll
    for (int i = 0; i < 4; i++) { rs[i][0] = rs[i][1] = 0.f; cs[i][0] = cs[i][1] = 0.f; }

    int RM = wm * 64, CN = wn * 32;
    #pragma unroll
    for (int mt = 0; mt < 4; mt++) {
        int r0 = RM + mt * 16 + (lane >> 2);
        int r1 = r0 + 8;
        #pragma unroll
        for (int nt = 0; nt < 4; nt++) {
            int c0 = CN + nt * 8 + ((lane & 3) << 1);
            int c1 = c0 + 1;
            float e0 = __expf((acc[mt][nt][0] - 1.0f) * INV_T);
            float e1 = __expf((acc[mt][nt][1] - 1.0f) * INV_T);
            float e2 = __expf((acc[mt][nt][2] - 1.0f) * INV_T);
            float e3 = __expf((acc[mt][nt][3] - 1.0f) * INV_T);
            if (diag) {
                if (r0 == c0) e0 = 0.f;
                if (r0 == c1) e1 = 0.f;
                if (r1 == c0) e2 = 0.f;
                if (r1 == c1) e3 = 0.f;
            }
            rs[mt][0] += e0 + e1;
            rs[mt][1] += e2 + e3;
            cs[nt][0] += e0 + e2;
            cs[nt][1] += e1 + e3;
        }
    }
    // row sums: reduce over lane bits 0-1 (the 4 col-threads per row)
    #pragma unroll
    for (int mt = 0; mt < 4; mt++) {
        #pragma unroll
        for (int h = 0; h < 2; h++) {
            rs[mt][h] += __shfl_xor_sync(0xffffffffu, rs[mt][h], 1);
            rs[mt][h] += __shfl_xor_sync(0xffffffffu, rs[mt][h], 2);
        }
        if ((lane & 3) == 0) {
            rbuf[RM + mt * 16 + (lane >> 2)][wn]     = rs[mt][0];
            rbuf[RM + mt * 16 + (lane >> 2) + 8][wn] = rs[mt][1];
        }
    }
    // col sums: reduce over lane bits 2-4 (the 8 row-threads per col)
    #pragma unroll
    for (int nt = 0; nt < 4; nt++) {
        #pragma unroll
        for (int v = 0; v < 2; v++) {
            cs[nt][v] += __shfl_xor_sync(0xffffffffu, cs[nt][v], 4);
            cs[nt][v] += __shfl_xor_sync(0xffffffffu, cs[nt][v], 8);
            cs[nt][v] += __shfl_xor_sync(0xffffffffu, cs[nt][v], 16);
        }
        if (lane < 4) {
            cbuf[CN + nt * 8 + lane * 2][wm]     = cs[nt][0];
            cbuf[CN + nt * 8 + lane * 2 + 1][wm] = cs[nt][1];
        }
    }
    __syncthreads();
    if (tid < 128) {
        float s = rbuf[tid][0] + rbuf[tid][1] + rbuf[tid][2] + rbuf[tid][3];
        g_Epart[bx][by * 128 + tid] = s;
    } else if (!diag) {
        int c = tid - 128;
        g_Epart[by][bx * 128 + c] = cbuf[c][0] + cbuf[c][1];
    }
    #undef LOADC
}

// ---------------- 4. per-row finalize ----------------
__global__ void finalize_kernel() {
    int warp = threadIdx.x >> 5, lane = threadIdx.x & 31;
    int row = blockIdx.x * 8 + warp;

    float E = g_Epart[lane][row] + g_Epart[lane + 32][row];

    int gl = g_glab[row];
    const float* f = g_fnorm + (size_t)row * DIM;
    const float* s = g_S + gl * DIM;
    float dss = 0.f, dii = 0.f;
    for (int d = lane; d < DIM; d += 32) {
        float fv = f[d];
        dss += fv * s[d];
        dii += fv * fv;
    }
    #pragma unroll
    for (int o = 16; o; o >>= 1) {
        E   += __shfl_xor_sync(0xffffffffu, E, o);
        dss += __shfl_xor_sync(0xffffffffu, dss, o);
        dii += __shfl_xor_sync(0xffffffffu, dii, o);
    }
    if (lane == 0) {
        int c = g_cnt[gl] - 1;
        float P = (dss - dii) * INV_T;
        float denom = E + 1e-8f;
        float cf = (float)c;
        float cm = fmaxf(cf, 1.0f);
        float mean = (P - cf * INV_T - cf * logf(denom)) / cm;
        g_psamp[row] = (c > 0) ? -mean : 0.0f;
        g_validv[row] = (c > 0) ? 1 : 0;
    }
}

// ---------------- 5. final reduce ----------------
__global__ void reduce_kernel(float* __restrict__ out) {
    __shared__ float shs[32];
    __shared__ int   shv[32];
    float s = 0.f;
    int v = 0;
    for (int i = threadIdx.x; i < NROWS; i += blockDim.x) {
        s += g_psamp[i];
        v += g_validv[i];
    }
    #pragma unroll
    for (int o = 16; o; o >>= 1) {
        s += __shfl_xor_sync(0xffffffffu, s, o);
        v += __shfl_xor_sync(0xffffffffu, v, o);
    }
    int wid = threadIdx.x >> 5, lane = threadIdx.x & 31;
    if (lane == 0) { shs[wid] = s; shv[wid] = v; }
    __syncthreads();
    if (threadIdx.x == 0) {
        float ts = 0.f; int tv = 0;
        int nw = blockDim.x >> 5;
        for (int w = 0; w < nw; w++) { ts += shs[w]; tv += shv[w]; }
        out[0] = ts / fmaxf((float)tv, 1.0f);
    }
}

// ---------------- launch ----------------
extern "C" void kernel_launch(void* const* d_in, const int* in_sizes, int n_in,
                              void* d_out, int out_size) {
    const float* feat   = (const float*)d_in[0];
    const int*   labels = (const int*)d_in[1];
    const int*   kptr   = (const int*)d_in[2];
    float* out = (float*)d_out;

    cudaFuncSetAttribute(classpart_kernel, cudaFuncAttributeMaxDynamicSharedMemorySize,
                         NCLS * DIM * (int)sizeof(float));

    norm_kernel<<<NROWS, 128>>>(feat, labels, kptr);
    classpart_kernel<<<NSLICE, 512, NCLS * DIM * sizeof(float)>>>();
    classred_kernel<<<NCLS, DIM>>>();
    count_kernel<<<1, 1024>>>();
    simexp_mma<<<NTRI, 256>>>();
    finalize_kernel<<<NROWS / 8, 256>>>();
    reduce_kernel<<<1, 1024>>>(out);
}